// round 16
// baseline (speedup 1.0000x reference)
#include <cuda_runtime.h>

#define NQ      14
#define DIM     (1 << NQ)       // 16384 amplitudes
#define HALF    (DIM / 2)       // 8192 packed (x,y) u64-pair slots
#define NL      8
#define NGATES  ((NL + 1) * NQ) // 126 single-qubit gates
#define THREADS 512

typedef unsigned long long u64;

// XOR swizzle on slot index; all passes use the same mapping.
__device__ __forceinline__ int phys64(int p) { return p ^ ((p >> 4) & 15); }

__device__ __forceinline__ u64 pk2(float lo, float hi) {
    u64 r; asm("mov.b64 %0, {%1,%2};" : "=l"(r) : "f"(lo), "f"(hi)); return r;
}
__device__ __forceinline__ void upk2(u64 v, float& lo, float& hi) {
    asm("mov.b64 {%0,%1}, %2;" : "=f"(lo), "=f"(hi) : "l"(v));
}
__device__ __forceinline__ u64 swap2(u64 v) {
    float lo, hi; upk2(v, lo, hi); return pk2(hi, lo);
}
__device__ __forceinline__ u64 fma2(u64 a, u64 b, u64 c) {
    u64 d; asm("fma.rn.f32x2 %0, %1, %2, %3;" : "=l"(d) : "l"(a), "l"(b), "l"(c));
    return d;
}
__device__ __forceinline__ u64 mul2(u64 a, u64 b) {
    u64 d; asm("mul.rn.f32x2 %0, %1, %2;" : "=l"(d) : "l"(a), "l"(b));
    return d;
}

// ---- UNSCALED Rx butterflies with t = tan(qx/2); the dropped factor
// c = cos(qx/2) is accumulated per layer and folded into the merged Rz
// diagonal (layers 1..7) or the final expectation (layer 8).
// new0: x = x0 + t*y1 ; y = y0 - t*x1
// new1: x = x1 + t*y0 ; y = y1 - t*x0

// Broadcast: partners are distinct packed elements (bit BIT of j, 16 elems).
template<int BIT>
__device__ __forceinline__ void rx_bcast(u64* PX, u64* PY, float t) {
    const u64 Tp = pk2(t, t);
    const u64 Tn = pk2(-t, -t);
    #pragma unroll
    for (int j = 0; j < 16; j++) {
        if (j & (1 << BIT)) continue;
        const int j2 = j | (1 << BIT);
        u64 x0 = PX[j], y0 = PY[j], x1 = PX[j2], y1 = PY[j2];
        PX[j]  = fma2(Tp, y1, x0);
        PY[j]  = fma2(Tn, x1, y0);
        PX[j2] = fma2(Tp, y0, x1);
        PY[j2] = fma2(Tn, x0, y1);
    }
}

// Pair-form: partners are the two lanes of each packed element.
__device__ __forceinline__ void rx_pair(u64* PX, u64* PY, float t) {
    const u64 Tp = pk2(t, t);
    const u64 Tn = pk2(-t, -t);
    #pragma unroll
    for (int j = 0; j < 16; j++) {
        u64 sxw = swap2(PX[j]), syw = swap2(PY[j]);
        PX[j] = fma2(Tp, syw, PX[j]);   // lane0: x0 + t*y1 ; lane1: x1 + t*y0
        PY[j] = fma2(Tn, sxw, PY[j]);   // lane0: y0 - t*x1 ; lane1: y1 - t*x0
    }
}

// Shuffle-form: partners in lane (lane ^ mask); symmetric both sides:
// x' = x + t*y_partner ; y' = y - t*x_partner.
__device__ __forceinline__ void rx_shfl(u64* PX, u64* PY, float t, int mask) {
    const u64 Tp = pk2(t, t);
    const u64 Tn = pk2(-t, -t);
    #pragma unroll
    for (int j = 0; j < 16; j++) {
        u64 xp = __shfl_xor_sync(0xffffffffu, PX[j], mask);
        u64 yp = __shfl_xor_sync(0xffffffffu, PY[j], mask);
        PX[j] = fma2(Tp, yp, PX[j]);
        PY[j] = fma2(Tn, xp, PY[j]);
    }
}

// One CTA = one (batch, circuit) pair; 512 threads, 16 packed pairs each.
// LAYER 0 IS FREE (folded into the product-state init; its CNOT is layer 1's
// Gray gather). Layers 1..8, TWO SMEM passes each:
//   AB: Gray-fused gather; w13 (pair) + w12..w9 (bcast on j) +
//       w8..w4 (shuffle on lane bits 0..4 = slot bits 4..8); store canonical.
//   C:  w3..w0 (bcast on j) + scaled merged Rz diagonal; in-place.
__global__ void __launch_bounds__(THREADS, 1)
pqc_kernel(const float* __restrict__ x,
           const float* __restrict__ qx1, const float* __restrict__ qz1,
           const float* __restrict__ c1,
           const float* __restrict__ qx2, const float* __restrict__ qz2,
           const float* __restrict__ c2,
           float* __restrict__ out, int B)
{
    extern __shared__ ulonglong2 SP[];      // HALF slots = 128 KB
    __shared__ float  tg[NGATES];           // tan(qx/2) per gate
    __shared__ float  qzh[NGATES];          // qz/2
    __shared__ float  lsc[NL + 1];          // per-layer prod of cos(qx/2)
    __shared__ float2 ejt[16];              // per-layer j-part phase table
    __shared__ float2 a2[NQ][2];            // layer-0-transformed qubit amps
    __shared__ float2 jtab[16];             // init j-part complex products
    __shared__ float  csh[NQ];
    __shared__ float  wsum[THREADS / 32];

    const int tid  = threadIdx.x;
    const int b    = blockIdx.x;
    const int circ = blockIdx.y;

    const float* qx = circ ? qx2 : qx1;
    const float* qz = circ ? qz2 : qz1;
    const float* cc = circ ? c2  : c1;

    if (tid < NGATES) {
        float ax = 0.5f * qx[tid];
        tg[tid]  = tanf(ax);                // precise (one-time); |t| <= ~0.27
        qzh[tid] = 0.5f * qz[tid];
    }
    if (tid <= NL) {                        // per-layer cos product (scale)
        float p = 1.0f;
        #pragma unroll
        for (int w = 0; w < NQ; w++)
            p *= cosf(0.5f * qx[tid * NQ + w]);
        lsc[tid] = p;
    }
    if (tid < NQ) {
        csh[tid] = cc[tid];
        // per-wire init amp (cos th, sin th), th = 0.5f*pi(f32)*bit
        float bit = (x[b * NQ + tid] > 0.0f) ? 1.0f : 0.0f;
        float th  = 1.5707963705062866f * bit;
        float a0 = cosf(th), a1 = sinf(th);
        // fold layer-0 gate U = Rz(qz0)Rx(qx0) EXACTLY (full, scaled form)
        float ax = 0.5f * qx[tid];
        float az = 0.5f * qz[tid];
        float cx = cosf(ax), sx = sinf(ax);
        float pr = cosf(az), pii = -sinf(az);   // pm = (pr, pii), pp = conj
        float t0 = cx * a0, t1 = sx * a1, t2 = sx * a0, t3 = cx * a1;
        a2[tid][0] = make_float2(pr * t0 + pii * t1,  pii * t0 - pr * t1);
        a2[tid][1] = make_float2(pr * t3 - pii * t2, -pii * t3 - pr * t2);
    }
    __syncthreads();

    // init j-table: products over wires 9..12 (j bit (12-w) selects)
    if (tid < 16) {
        float2 q = a2[9][(tid >> 3) & 1];
        #pragma unroll
        for (int w = 10; w < 13; w++) {
            float2 aw = a2[w][(tid >> (12 - w)) & 1];
            q = make_float2(q.x * aw.x - q.y * aw.y,
                            q.x * aw.y + q.y * aw.x);
        }
        jtab[tid] = q;
    }

    // thread-part product over wires 0..8 (tid bit (8-w))
    float2 T = a2[0][(tid >> 8) & 1];
    #pragma unroll
    for (int w = 1; w < 9; w++) {
        float2 aw = a2[w][(tid >> (8 - w)) & 1];
        T = make_float2(T.x * aw.x - T.y * aw.y,
                        T.x * aw.y + T.y * aw.x);
    }
    __syncthreads();   // jtab ready

    u64 PX[16], PY[16];
    float local = 0.0f;

    // ---- init state = layer-0 output, straight into canonical layout ----
    {
        const float a13x0 = a2[13][0].x, a13y0 = a2[13][0].y;
        const float a13x1 = a2[13][1].x, a13y1 = a2[13][1].y;
        #pragma unroll
        for (int j = 0; j < 16; j++) {
            float2 jt = jtab[j];
            float qr = T.x * jt.x - T.y * jt.y;
            float qi = T.x * jt.y + T.y * jt.x;
            PX[j] = pk2(qr * a13x0 - qi * a13y0, qr * a13x1 - qi * a13y1);
            PY[j] = pk2(qr * a13y0 + qi * a13x0, qr * a13y1 + qi * a13x1);
            SP[phys64((tid << 4) | j)] = make_ulonglong2(PX[j], PY[j]);
        }
        __syncthreads();   // RAW for layer 1's Gray gather
    }

    for (int l = 1; l <= NL; l++) {
        const int gb = l * NQ;

        // ===== Pass AB: m = (tid<<4)|j. pair=w13; j bits 0..3 -> w12..w9;
        //       lane bit t = slot bit 4+t -> wire 8-t (shuffle masks 1..16).
        // Gray gather (prev layer's CNOT ladder): slot m <- slot m^(m>>1)
        #pragma unroll
        for (int j = 0; j < 16; j++) {
            int m  = (tid << 4) | j;
            int ps = m ^ (m >> 1);
            ulonglong2 v = SP[phys64(ps)];
            if (j & 1) { PX[j] = swap2(v.x); PY[j] = swap2(v.y); }
            else       { PX[j] = v.x;        PY[j] = v.y; }
        }
        rx_pair(PX, PY, tg[gb + 13]);
        rx_bcast<0>(PX, PY, tg[gb + 12]);
        rx_bcast<1>(PX, PY, tg[gb + 11]);
        rx_bcast<2>(PX, PY, tg[gb + 10]);
        rx_bcast<3>(PX, PY, tg[gb + 9]);
        rx_shfl(PX, PY, tg[gb + 8], 1);    // w8 <-> lane bit 0
        rx_shfl(PX, PY, tg[gb + 7], 2);    // w7 <-> lane bit 1
        rx_shfl(PX, PY, tg[gb + 6], 4);    // w6 <-> lane bit 2
        rx_shfl(PX, PY, tg[gb + 5], 8);    // w5 <-> lane bit 3
        rx_shfl(PX, PY, tg[gb + 4], 16);   // w4 <-> lane bit 4
        __syncthreads();                   // WAR: all gathers read first
        #pragma unroll
        for (int j = 0; j < 16; j++)
            SP[phys64((tid << 4) | j)] = make_ulonglong2(PX[j], PY[j]);
        // per-layer j-part phase table (pass-C j bit t <-> wire 3-t)
        if (l < NL && tid < 16) {
            float a = 0.0f;
            #pragma unroll
            for (int w = 0; w < 4; w++)
                a += ((tid >> (3 - w)) & 1) ? qzh[gb + w] : -qzh[gb + w];
            ejt[tid] = make_float2(__cosf(a), __sinf(a));
        }
        __syncthreads();                   // RAW for pass C (state + table)

        // ===== Pass C: p = (j<<9)|tid; j bits -> w3..w0; in-place =====
        {
            #pragma unroll
            for (int j = 0; j < 16; j++) {
                ulonglong2 v = SP[phys64((j << 9) | tid)];
                PX[j] = v.x; PY[j] = v.y;
            }
            rx_bcast<0>(PX, PY, tg[gb + 3]);
            rx_bcast<1>(PX, PY, tg[gb + 2]);
            rx_bcast<2>(PX, PY, tg[gb + 1]);
            rx_bcast<3>(PX, PY, tg[gb + 0]);

            if (l < NL) {
                // Merged Rz diagonal * layer scale lsc[l] (restores the cos
                // factors dropped by the unscaled butterflies).
                // i = (j<<10)|(tid<<1)|lane13: tid bits 8..0 <-> wires 4..12.
                float pht = 0.0f;
                #pragma unroll
                for (int w = 4; w < 13; w++)
                    pht += ((tid >> (12 - w)) & 1) ? qzh[gb + w] : -qzh[gb + w];
                const float z13 = qzh[gb + 13];
                const float sc  = lsc[l];
                const float aa0 = pht - z13, aa1 = pht + z13;
                const float c0 = __cosf(aa0) * sc, c1 = __cosf(aa1) * sc;
                const float s0 = __sinf(aa0) * sc, s1 = __sinf(aa1) * sc;
                const u64 Er  = pk2(c0, c1);
                const u64 Eip = pk2(s0, s1);
                const u64 Ein = pk2(-s0, -s1);
                #pragma unroll
                for (int j = 0; j < 16; j++) {
                    // apply scaled E (lane-dependent phase)
                    u64 nx = fma2(PX[j], Er, mul2(PY[j], Ein));
                    u64 ny = fma2(PY[j], Er, mul2(PX[j], Eip));
                    // apply ejt[j] (unit-modulus j-dependent phase)
                    const float ejr = ejt[j].x, eji = ejt[j].y;
                    const u64 EJR  = pk2(ejr,  ejr);
                    const u64 EJIp = pk2(eji,  eji);
                    const u64 EJIn = pk2(-eji, -eji);
                    PX[j] = fma2(nx, EJR, mul2(ny, EJIn));
                    PY[j] = fma2(ny, EJR, mul2(nx, EJIp));
                }
                #pragma unroll
                for (int j = 0; j < 16; j++)
                    SP[phys64((j << 9) | tid)] = make_ulonglong2(PX[j], PY[j]);
                __syncthreads();             // RAW for next layer's gather
            } else {
                // Last layer: diagonal is a pure phase -> skip; the missing
                // scale lsc[NL] enters squared via the probabilities.
                // Expectation. i = (j<<10)|(tid<<1)|lane13.
                float gt = 0.0f;
                #pragma unroll
                for (int w = 4; w < 13; w++)
                    gt += ((tid >> (12 - w)) & 1) ? -csh[w] : csh[w];
                const float c13 = csh[13];
                #pragma unroll
                for (int j = 0; j < 16; j++) {
                    float gj = 0.0f;
                    #pragma unroll
                    for (int w = 0; w < 4; w++)
                        gj += ((j >> (3 - w)) & 1) ? -csh[w] : csh[w];
                    float x0, x1, y0, y1;
                    upk2(PX[j], x0, x1); upk2(PY[j], y0, y1);
                    local += (x0 * x0 + y0 * y0) * (gt + gj + c13)
                           + (x1 * x1 + y1 * y1) * (gt + gj - c13);
                }
                local *= lsc[NL] * lsc[NL];
            }
        }
    }

    // deterministic reduction
    #pragma unroll
    for (int off = 16; off; off >>= 1)
        local += __shfl_down_sync(0xffffffffu, local, off);
    if ((tid & 31) == 0) wsum[tid >> 5] = local;
    __syncthreads();
    if (tid == 0) {
        float tot = 0.0f;
        #pragma unroll
        for (int i = 0; i < THREADS / 32; i++) tot += wsum[i];
        // PLANAR complex output: out[0..B) = real (f1), out[B..2B) = imag (f2)
        out[circ * B + b] = tot;
    }
}

extern "C" void kernel_launch(void* const* d_in, const int* in_sizes, int n_in,
                              void* d_out, int out_size)
{
    const float *x, *qx1, *qz1, *c1, *qx2, *qz2, *c2;

    if (n_in >= 7 && in_sizes[0] > 1000) {
        // dict order: x, q_x1, q_z1, c1, q_x2, q_z2, c2
        x   = (const float*)d_in[0];
        qx1 = (const float*)d_in[1];
        qz1 = (const float*)d_in[2];
        c1  = (const float*)d_in[3];
        qx2 = (const float*)d_in[4];
        qz2 = (const float*)d_in[5];
        c2  = (const float*)d_in[6];
    } else if (n_in >= 7 && in_sizes[0] == NQ && in_sizes[1] == NQ) {
        c1  = (const float*)d_in[0];
        c2  = (const float*)d_in[1];
        qx1 = (const float*)d_in[2];
        qx2 = (const float*)d_in[3];
        qz1 = (const float*)d_in[4];
        qz2 = (const float*)d_in[5];
        x   = (const float*)d_in[6];
    } else {
        const float* qs[4] = {0, 0, 0, 0};
        const float* cs[2] = {0, 0};
        const float* xp = 0;
        int nq = 0, nc = 0;
        for (int i = 0; i < n_in; i++) {
            if (in_sizes[i] > 1000)         xp = (const float*)d_in[i];
            else if (in_sizes[i] == NGATES) { if (nq < 4) qs[nq++] = (const float*)d_in[i]; }
            else if (in_sizes[i] == NQ)     { if (nc < 2) cs[nc++] = (const float*)d_in[i]; }
        }
        x = xp; qx1 = qs[0]; qz1 = qs[1]; qx2 = qs[2]; qz2 = qs[3];
        c1 = cs[0]; c2 = cs[1];
    }

    int xsz = 0;
    for (int i = 0; i < n_in; i++) if (in_sizes[i] > xsz) xsz = in_sizes[i];
    const int B = xsz / NQ;  // 256

    cudaFuncSetAttribute(pqc_kernel,
                         cudaFuncAttributeMaxDynamicSharedMemorySize,
                         HALF * sizeof(ulonglong2));   // 128 KB interleaved

    dim3 grid(B, 2);
    pqc_kernel<<<grid, THREADS, HALF * sizeof(ulonglong2)>>>(
        x, qx1, qz1, c1, qx2, qz2, c2, (float*)d_out, B);
}

// round 17
// speedup vs baseline: 1.1662x; 1.1662x over previous
#include <cuda_runtime.h>

#define NQ      14
#define DIM     (1 << NQ)       // 16384 amplitudes
#define HALF    (DIM / 2)       // 8192 packed (x,y) u64-pair slots
#define NL      8
#define NGATES  ((NL + 1) * NQ) // 126 single-qubit gates
#define THREADS 512

typedef unsigned long long u64;

// XOR swizzle on slot index; all passes use the same mapping.
__device__ __forceinline__ int phys64(int p) { return p ^ ((p >> 4) & 15); }

__device__ __forceinline__ u64 pk2(float lo, float hi) {
    u64 r; asm("mov.b64 %0, {%1,%2};" : "=l"(r) : "f"(lo), "f"(hi)); return r;
}
__device__ __forceinline__ void upk2(u64 v, float& lo, float& hi) {
    asm("mov.b64 {%0,%1}, %2;" : "=f"(lo), "=f"(hi) : "l"(v));
}
__device__ __forceinline__ u64 swap2(u64 v) {
    float lo, hi; upk2(v, lo, hi); return pk2(hi, lo);
}
__device__ __forceinline__ u64 fma2(u64 a, u64 b, u64 c) {
    u64 d; asm("fma.rn.f32x2 %0, %1, %2, %3;" : "=l"(d) : "l"(a), "l"(b), "l"(c));
    return d;
}
__device__ __forceinline__ u64 mul2(u64 a, u64 b) {
    u64 d; asm("mul.rn.f32x2 %0, %1, %2;" : "=l"(d) : "l"(a), "l"(b));
    return d;
}

// ---- UNSCALED Rx butterflies with t = tan(qx/2); the dropped factor
// c = cos(qx/2) is folded into the merged Rz diagonal (layers 1..7) or the
// final expectation (layer 8).
// new0: x = x0 + t*y1 ; y = y0 - t*x1
// new1: x = x1 + t*y0 ; y = y1 - t*x0

// One butterfly between register elements a and b (compile-time indices).
#define BF(a, b, Tp, Tn) do {                                   \
    u64 _x0 = PX[a], _y0 = PY[a], _x1 = PX[b], _y1 = PY[b];     \
    PX[a] = fma2(Tp, _y1, _x0);  PY[a] = fma2(Tn, _x1, _y0);    \
    PX[b] = fma2(Tp, _y0, _x1);  PY[b] = fma2(Tn, _x0, _y1);    \
} while (0)

// bit0 + bit1 gates on one quartet [c..c+3]
#define STAGE01(c, T0p, T0n, T1p, T1n) do {                     \
    BF((c),     (c) + 1, T0p, T0n);                             \
    BF((c) + 2, (c) + 3, T0p, T0n);                             \
    BF((c),     (c) + 2, T1p, T1n);                             \
    BF((c) + 1, (c) + 3, T1p, T1n);                             \
} while (0)

// bit2 gate on one octet starting at c
#define OCT(c, Tp, Tn) do {                                     \
    BF((c),     (c) + 4, Tp, Tn);  BF((c) + 1, (c) + 5, Tp, Tn);\
    BF((c) + 2, (c) + 6, Tp, Tn);  BF((c) + 3, (c) + 7, Tp, Tn);\
} while (0)

// bit3 gate on all 16
#define HEX(Tp, Tn) do {                                        \
    BF(0, 8,  Tp, Tn); BF(1, 9,  Tp, Tn);                       \
    BF(2, 10, Tp, Tn); BF(3, 11, Tp, Tn);                       \
    BF(4, 12, Tp, Tn); BF(5, 13, Tp, Tn);                       \
    BF(6, 14, Tp, Tn); BF(7, 15, Tp, Tn);                       \
} while (0)

// pair-form (lane) gate on one quartet
#define PAIR4(c, Tp, Tn) do {                                   \
    _Pragma("unroll")                                           \
    for (int _j = (c); _j < (c) + 4; _j++) {                    \
        u64 _sx = swap2(PX[_j]), _sy = swap2(PY[_j]);           \
        PX[_j] = fma2(Tp, _sy, PX[_j]);                         \
        PY[_j] = fma2(Tn, _sx, PY[_j]);                         \
    }                                                           \
} while (0)

// shuffle-form gate (mask 16) on one quartet
#define SHFL4(c, Tp, Tn) do {                                   \
    _Pragma("unroll")                                           \
    for (int _j = (c); _j < (c) + 4; _j++) {                    \
        u64 _xp = __shfl_xor_sync(0xffffffffu, PX[_j], 16);     \
        u64 _yp = __shfl_xor_sync(0xffffffffu, PY[_j], 16);     \
        PX[_j] = fma2(Tp, _yp, PX[_j]);                         \
        PY[_j] = fma2(Tn, _xp, PY[_j]);                         \
    }                                                           \
} while (0)

// Gray-fused gather of one quartet (pass A)
#define GATH4(c) do {                                           \
    _Pragma("unroll")                                           \
    for (int _j = (c); _j < (c) + 4; _j++) {                    \
        int _m = (tid << 4) | _j, _ps = _m ^ (_m >> 1);         \
        ulonglong2 _v = SP[phys64(_ps)];                        \
        if (_j & 1) { PX[_j] = swap2(_v.x); PY[_j] = swap2(_v.y); } \
        else        { PX[_j] = _v.x;        PY[_j] = _v.y; }    \
    }                                                           \
} while (0)

// One CTA = one (batch, circuit) pair; 512 threads, 16 packed pairs each.
// LAYER 0 IS FREE (folded into the product-state init; its CNOT is layer 1's
// Gray gather). Layers 1..8, three passes, each SOFTWARE-PIPELINED in
// quartets so loads of chunk k+1 overlap gates of chunk k:
//   A: gather + w13(pair) + w12..w9 (decimation bcast)
//   B: w8..w5 (bcast) + w4 (shfl16), in-place
//   C: w3..w0 (bcast) + scaled merged Rz diagonal, in-place
__global__ void __launch_bounds__(THREADS, 1)
pqc_kernel(const float* __restrict__ x,
           const float* __restrict__ qx1, const float* __restrict__ qz1,
           const float* __restrict__ c1,
           const float* __restrict__ qx2, const float* __restrict__ qz2,
           const float* __restrict__ c2,
           float* __restrict__ out, int B)
{
    extern __shared__ ulonglong2 SP[];      // HALF slots = 128 KB
    __shared__ float  tg[NGATES];           // tan(qx/2) per gate
    __shared__ float  qzh[NGATES];          // qz/2
    __shared__ float  lsc[NL + 1];          // per-layer prod of cos(qx/2)
    __shared__ float2 ejt[16];              // per-layer j-part phase table
    __shared__ float2 a2[NQ][2];            // layer-0-transformed qubit amps
    __shared__ float2 jtab[16];             // init j-part complex products
    __shared__ float  csh[NQ];
    __shared__ float  wsum[THREADS / 32];

    const int tid  = threadIdx.x;
    const int b    = blockIdx.x;
    const int circ = blockIdx.y;

    const float* qx = circ ? qx2 : qx1;
    const float* qz = circ ? qz2 : qz1;
    const float* cc = circ ? c2  : c1;

    if (tid < NGATES) {
        float ax = 0.5f * qx[tid];
        tg[tid]  = tanf(ax);                // precise (one-time); |t| <= ~0.27
        qzh[tid] = 0.5f * qz[tid];
    }
    if (tid <= NL) {                        // per-layer cos product (scale)
        float p = 1.0f;
        #pragma unroll
        for (int w = 0; w < NQ; w++)
            p *= cosf(0.5f * qx[tid * NQ + w]);
        lsc[tid] = p;
    }
    if (tid < NQ) {
        csh[tid] = cc[tid];
        // per-wire init amp (cos th, sin th), th = 0.5f*pi(f32)*bit
        float bit = (x[b * NQ + tid] > 0.0f) ? 1.0f : 0.0f;
        float th  = 1.5707963705062866f * bit;
        float a0 = cosf(th), a1 = sinf(th);
        // fold layer-0 gate U = Rz(qz0)Rx(qx0) EXACTLY (full, scaled form)
        float ax = 0.5f * qx[tid];
        float az = 0.5f * qz[tid];
        float cx = cosf(ax), sx = sinf(ax);
        float pr = cosf(az), pii = -sinf(az);   // pm = (pr, pii), pp = conj
        float t0 = cx * a0, t1 = sx * a1, t2 = sx * a0, t3 = cx * a1;
        a2[tid][0] = make_float2(pr * t0 + pii * t1,  pii * t0 - pr * t1);
        a2[tid][1] = make_float2(pr * t3 - pii * t2, -pii * t3 - pr * t2);
    }
    __syncthreads();

    // init j-table: products over wires 9..12 (j bit (12-w) selects)
    if (tid < 16) {
        float2 q = a2[9][(tid >> 3) & 1];
        #pragma unroll
        for (int w = 10; w < 13; w++) {
            float2 aw = a2[w][(tid >> (12 - w)) & 1];
            q = make_float2(q.x * aw.x - q.y * aw.y,
                            q.x * aw.y + q.y * aw.x);
        }
        jtab[tid] = q;
    }

    // thread-part product over wires 0..8 (tid bit (8-w))
    float2 T = a2[0][(tid >> 8) & 1];
    #pragma unroll
    for (int w = 1; w < 9; w++) {
        float2 aw = a2[w][(tid >> (8 - w)) & 1];
        T = make_float2(T.x * aw.x - T.y * aw.y,
                        T.x * aw.y + T.y * aw.x);
    }
    __syncthreads();   // jtab ready

    u64 PX[16], PY[16];
    float local = 0.0f;

    // ---- init state = layer-0 output, straight into canonical layout ----
    {
        const float a13x0 = a2[13][0].x, a13y0 = a2[13][0].y;
        const float a13x1 = a2[13][1].x, a13y1 = a2[13][1].y;
        #pragma unroll
        for (int j = 0; j < 16; j++) {
            float2 jt = jtab[j];
            float qr = T.x * jt.x - T.y * jt.y;
            float qi = T.x * jt.y + T.y * jt.x;
            PX[j] = pk2(qr * a13x0 - qi * a13y0, qr * a13x1 - qi * a13y1);
            PY[j] = pk2(qr * a13y0 + qi * a13x0, qr * a13y1 + qi * a13x1);
            SP[phys64((tid << 4) | j)] = make_ulonglong2(PX[j], PY[j]);
        }
        __syncthreads();   // RAW for layer 1's Gray gather
    }

    for (int l = 1; l <= NL; l++) {
        const int gb = l * NQ;

        // ===== Pass A: m = (tid<<4)|j. pair=w13; j bits 0..3 -> w12..w9 ====
        {
            const float v13 = tg[gb + 13], v12 = tg[gb + 12], v11 = tg[gb + 11];
            const float v10 = tg[gb + 10], v9  = tg[gb + 9];
            const u64 T13p = pk2(v13, v13), T13n = pk2(-v13, -v13);
            const u64 T12p = pk2(v12, v12), T12n = pk2(-v12, -v12);
            const u64 T11p = pk2(v11, v11), T11n = pk2(-v11, -v11);
            const u64 T10p = pk2(v10, v10), T10n = pk2(-v10, -v10);
            const u64 T9p  = pk2(v9,  v9),  T9n  = pk2(-v9,  -v9);

            GATH4(0);  PAIR4(0,  T13p, T13n); STAGE01(0,  T12p, T12n, T11p, T11n);
            GATH4(4);  PAIR4(4,  T13p, T13n); STAGE01(4,  T12p, T12n, T11p, T11n);
            OCT(0, T10p, T10n);
            GATH4(8);  PAIR4(8,  T13p, T13n); STAGE01(8,  T12p, T12n, T11p, T11n);
            GATH4(12); PAIR4(12, T13p, T13n); STAGE01(12, T12p, T12n, T11p, T11n);
            OCT(8, T10p, T10n);
            HEX(T9p, T9n);
        }
        __syncthreads();                   // WAR: all gathers read first
        #pragma unroll
        for (int j = 0; j < 16; j++)
            SP[phys64((tid << 4) | j)] = make_ulonglong2(PX[j], PY[j]);
        // A->B exchange is provably intra-warp (writer tids share warp).
        __syncwarp();

        // ===== Pass B: p = (thi<<8)|(j<<4)|tlo; j -> w8..w5; w4 = shfl16 ===
        {
            const int thi = tid >> 4, tlo = tid & 15;
            const int pbase = (thi << 8) | tlo;
            const float v8 = tg[gb + 8], v7 = tg[gb + 7], v6 = tg[gb + 6];
            const float v5 = tg[gb + 5], v4 = tg[gb + 4];
            const u64 T8p = pk2(v8, v8), T8n = pk2(-v8, -v8);
            const u64 T7p = pk2(v7, v7), T7n = pk2(-v7, -v7);
            const u64 T6p = pk2(v6, v6), T6n = pk2(-v6, -v6);
            const u64 T5p = pk2(v5, v5), T5n = pk2(-v5, -v5);
            const u64 T4p = pk2(v4, v4), T4n = pk2(-v4, -v4);

            #define LOADB4(c)                                           \
                _Pragma("unroll")                                       \
                for (int _j = (c); _j < (c) + 4; _j++) {                \
                    ulonglong2 _v = SP[phys64(pbase | (_j << 4))];      \
                    PX[_j] = _v.x; PY[_j] = _v.y;                       \
                }
            LOADB4(0);  STAGE01(0,  T8p, T8n, T7p, T7n);
            LOADB4(4);  STAGE01(4,  T8p, T8n, T7p, T7n);
            OCT(0, T6p, T6n);
            LOADB4(8);  STAGE01(8,  T8p, T8n, T7p, T7n);
            LOADB4(12); STAGE01(12, T8p, T8n, T7p, T7n);
            OCT(8, T6p, T6n);
            HEX(T5p, T5n);
            #undef LOADB4

            // w4 shuffle + in-place store, chunked (same slots read -> no WAR)
            #pragma unroll
            for (int c = 0; c < 16; c += 4) {
                SHFL4(c, T4p, T4n);
                #pragma unroll
                for (int j = c; j < c + 4; j++)
                    SP[phys64(pbase | (j << 4))] = make_ulonglong2(PX[j], PY[j]);
            }
            // per-layer j-part phase table (pass-C j bit t <-> wire 3-t)
            if (l < NL && tid < 16) {
                float a = 0.0f;
                #pragma unroll
                for (int w = 0; w < 4; w++)
                    a += ((tid >> (3 - w)) & 1) ? qzh[gb + w] : -qzh[gb + w];
                ejt[tid] = make_float2(__cosf(a), __sinf(a));
            }
            __syncthreads();               // RAW for pass C (state + table)
        }

        // ===== Pass C: p = (j<<9)|tid; j bits -> w3..w0; in-place =========
        {
            const float v3 = tg[gb + 3], v2 = tg[gb + 2];
            const float v1 = tg[gb + 1], v0 = tg[gb + 0];
            const u64 T3p = pk2(v3, v3), T3n = pk2(-v3, -v3);
            const u64 T2p = pk2(v2, v2), T2n = pk2(-v2, -v2);
            const u64 T1p = pk2(v1, v1), T1n = pk2(-v1, -v1);
            const u64 T0p = pk2(v0, v0), T0n = pk2(-v0, -v0);

            #define LOADC4(c)                                           \
                _Pragma("unroll")                                       \
                for (int _j = (c); _j < (c) + 4; _j++) {                \
                    ulonglong2 _v = SP[phys64((_j << 9) | tid)];        \
                    PX[_j] = _v.x; PY[_j] = _v.y;                       \
                }
            LOADC4(0);  STAGE01(0,  T3p, T3n, T2p, T2n);
            LOADC4(4);  STAGE01(4,  T3p, T3n, T2p, T2n);
            OCT(0, T1p, T1n);
            LOADC4(8);  STAGE01(8,  T3p, T3n, T2p, T2n);
            LOADC4(12); STAGE01(12, T3p, T3n, T2p, T2n);
            OCT(8, T1p, T1n);
            HEX(T0p, T0n);
            #undef LOADC4

            if (l < NL) {
                // Merged Rz diagonal * layer scale lsc[l] (restores the cos
                // factors dropped by the unscaled butterflies).
                // i = (j<<10)|(tid<<1)|lane13: tid bits 8..0 <-> wires 4..12.
                float pht = 0.0f;
                #pragma unroll
                for (int w = 4; w < 13; w++)
                    pht += ((tid >> (12 - w)) & 1) ? qzh[gb + w] : -qzh[gb + w];
                const float z13 = qzh[gb + 13];
                const float sc  = lsc[l];
                const float aa0 = pht - z13, aa1 = pht + z13;
                const float c0 = __cosf(aa0) * sc, c1 = __cosf(aa1) * sc;
                const float s0 = __sinf(aa0) * sc, s1 = __sinf(aa1) * sc;
                const u64 Er  = pk2(c0, c1);
                const u64 Eip = pk2(s0, s1);
                const u64 Ein = pk2(-s0, -s1);
                // diag + in-place store, chunked
                #pragma unroll
                for (int c = 0; c < 16; c += 4) {
                    #pragma unroll
                    for (int j = c; j < c + 4; j++) {
                        u64 nx = fma2(PX[j], Er, mul2(PY[j], Ein));
                        u64 ny = fma2(PY[j], Er, mul2(PX[j], Eip));
                        const float ejr = ejt[j].x, eji = ejt[j].y;
                        const u64 EJR  = pk2(ejr,  ejr);
                        const u64 EJIp = pk2(eji,  eji);
                        const u64 EJIn = pk2(-eji, -eji);
                        PX[j] = fma2(nx, EJR, mul2(ny, EJIn));
                        PY[j] = fma2(ny, EJR, mul2(nx, EJIp));
                        SP[phys64((j << 9) | tid)] = make_ulonglong2(PX[j], PY[j]);
                    }
                }
                __syncthreads();             // RAW for next layer's gather
            } else {
                // Last layer: diagonal is a pure phase -> skip; the missing
                // scale lsc[NL] enters squared via the probabilities.
                // Expectation. i = (j<<10)|(tid<<1)|lane13.
                float gt = 0.0f;
                #pragma unroll
                for (int w = 4; w < 13; w++)
                    gt += ((tid >> (12 - w)) & 1) ? -csh[w] : csh[w];
                const float c13 = csh[13];
                #pragma unroll
                for (int j = 0; j < 16; j++) {
                    float gj = 0.0f;
                    #pragma unroll
                    for (int w = 0; w < 4; w++)
                        gj += ((j >> (3 - w)) & 1) ? -csh[w] : csh[w];
                    float x0, x1, y0, y1;
                    upk2(PX[j], x0, x1); upk2(PY[j], y0, y1);
                    local += (x0 * x0 + y0 * y0) * (gt + gj + c13)
                           + (x1 * x1 + y1 * y1) * (gt + gj - c13);
                }
                local *= lsc[NL] * lsc[NL];
            }
        }
    }

    // deterministic reduction
    #pragma unroll
    for (int off = 16; off; off >>= 1)
        local += __shfl_down_sync(0xffffffffu, local, off);
    if ((tid & 31) == 0) wsum[tid >> 5] = local;
    __syncthreads();
    if (tid == 0) {
        float tot = 0.0f;
        #pragma unroll
        for (int i = 0; i < THREADS / 32; i++) tot += wsum[i];
        // PLANAR complex output: out[0..B) = real (f1), out[B..2B) = imag (f2)
        out[circ * B + b] = tot;
    }
}

extern "C" void kernel_launch(void* const* d_in, const int* in_sizes, int n_in,
                              void* d_out, int out_size)
{
    const float *x, *qx1, *qz1, *c1, *qx2, *qz2, *c2;

    if (n_in >= 7 && in_sizes[0] > 1000) {
        // dict order: x, q_x1, q_z1, c1, q_x2, q_z2, c2
        x   = (const float*)d_in[0];
        qx1 = (const float*)d_in[1];
        qz1 = (const float*)d_in[2];
        c1  = (const float*)d_in[3];
        qx2 = (const float*)d_in[4];
        qz2 = (const float*)d_in[5];
        c2  = (const float*)d_in[6];
    } else if (n_in >= 7 && in_sizes[0] == NQ && in_sizes[1] == NQ) {
        c1  = (const float*)d_in[0];
        c2  = (const float*)d_in[1];
        qx1 = (const float*)d_in[2];
        qx2 = (const float*)d_in[3];
        qz1 = (const float*)d_in[4];
        qz2 = (const float*)d_in[5];
        x   = (const float*)d_in[6];
    } else {
        const float* qs[4] = {0, 0, 0, 0};
        const float* cs[2] = {0, 0};
        const float* xp = 0;
        int nq = 0, nc = 0;
        for (int i = 0; i < n_in; i++) {
            if (in_sizes[i] > 1000)         xp = (const float*)d_in[i];
            else if (in_sizes[i] == NGATES) { if (nq < 4) qs[nq++] = (const float*)d_in[i]; }
            else if (in_sizes[i] == NQ)     { if (nc < 2) cs[nc++] = (const float*)d_in[i]; }
        }
        x = xp; qx1 = qs[0]; qz1 = qs[1]; qx2 = qs[2]; qz2 = qs[3];
        c1 = cs[0]; c2 = cs[1];
    }

    int xsz = 0;
    for (int i = 0; i < n_in; i++) if (in_sizes[i] > xsz) xsz = in_sizes[i];
    const int B = xsz / NQ;  // 256

    cudaFuncSetAttribute(pqc_kernel,
                         cudaFuncAttributeMaxDynamicSharedMemorySize,
                         HALF * sizeof(ulonglong2));   // 128 KB interleaved

    dim3 grid(B, 2);
    pqc_kernel<<<grid, THREADS, HALF * sizeof(ulonglong2)>>>(
        x, qx1, qz1, c1, qx2, qz2, c2, (float*)d_out, B);
}